// round 14
// baseline (speedup 1.0000x reference)
#include <cuda_runtime.h>
#include <cuda_fp16.h>
#include <stdint.h>

#define N_NODES 100000
#define N_EDGES 1600000
#define D_FEAT  64

// Scratch (device globals — no allocs allowed):
__device__ int    g_row_ptr[N_NODES + 1];
__device__ __half g_emb_h[N_NODES * D_FEAT];   // 12.8 MB fp16 shadow (128B per row)

// Merged prep: fp32->fp16 convert (16 floats/thread, MLP=4) AND CSR fill.
__global__ void prep_kernel(const float* __restrict__ embeds,
                            const int*   __restrict__ rows,
                            int n_edges) {
    int i = blockIdx.x * blockDim.x + threadIdx.x;

    // Task 1: convert 16 floats -> 16 halfs (4 independent float4 loads)
    if (i < N_NODES * D_FEAT / 16) {
        const float4* src = reinterpret_cast<const float4*>(embeds) + (size_t)i * 4;
        float4 f0 = src[0];
        float4 f1 = src[1];
        float4 f2 = src[2];
        float4 f3 = src[3];
        union { __half2 h[4]; uint4 u; } a, b;
        a.h[0] = __floats2half2_rn(f0.x, f0.y);
        a.h[1] = __floats2half2_rn(f0.z, f0.w);
        a.h[2] = __floats2half2_rn(f1.x, f1.y);
        a.h[3] = __floats2half2_rn(f1.z, f1.w);
        b.h[0] = __floats2half2_rn(f2.x, f2.y);
        b.h[1] = __floats2half2_rn(f2.z, f2.w);
        b.h[2] = __floats2half2_rn(f3.x, f3.y);
        b.h[3] = __floats2half2_rn(f3.z, f3.w);
        reinterpret_cast<uint4*>(g_emb_h)[i * 2]     = a.u;
        reinterpret_cast<uint4*>(g_emb_h)[i * 2 + 1] = b.u;
    }

    // Task 2: row_ptr boundary fill (rows sorted)
    if (i < n_edges) {
        int r = rows[i];
        int prev = (i == 0) ? -1 : rows[i - 1];
        for (int rr = prev + 1; rr <= r; ++rr) {
            g_row_ptr[rr] = i;
        }
        if (i == n_edges - 1) {
            for (int rr = r + 1; rr <= N_NODES; ++rr) {
                g_row_ptr[rr] = n_edges;
            }
        }
    }
}

// fp32-exact single-edge accumulate (peel/tail path).
__device__ __forceinline__ void edge_f32(const uint4* __restrict__ emb,
                                         const int* __restrict__ cols,
                                         const float* __restrict__ vals,
                                         int e, int lane8,
                                         float4& aA, float4& aB) {
    int   c = cols[e];
    float v = vals[e];
    uint4 r = emb[(size_t)c * 8 + lane8];
    float2 f0 = __half22float2(*reinterpret_cast<__half2*>(&r.x));
    float2 f1 = __half22float2(*reinterpret_cast<__half2*>(&r.y));
    float2 f2 = __half22float2(*reinterpret_cast<__half2*>(&r.z));
    float2 f3 = __half22float2(*reinterpret_cast<__half2*>(&r.w));
    aA.x += v * f0.x;  aA.y += v * f0.y;
    aA.z += v * f1.x;  aA.w += v * f1.y;
    aB.x += v * f2.x;  aB.y += v * f2.y;
    aB.z += v * f3.x;  aB.w += v * f3.y;
}

// depth-4 half2 chain over 4 pre-loaded gathers, then fp32 drain.
__device__ __forceinline__ void chain4_drain(const uint4& r0, const uint4& r1,
                                             const uint4& r2, const uint4& r3,
                                             __half2 h0, __half2 h1,
                                             __half2 h2, __half2 h3,
                                             float4& aA, float4& aB) {
    __half2 p0 = __hmul2(h0, *reinterpret_cast<const __half2*>(&r0.x));
    __half2 p1 = __hmul2(h0, *reinterpret_cast<const __half2*>(&r0.y));
    __half2 p2 = __hmul2(h0, *reinterpret_cast<const __half2*>(&r0.z));
    __half2 p3 = __hmul2(h0, *reinterpret_cast<const __half2*>(&r0.w));
    p0 = __hfma2(h1, *reinterpret_cast<const __half2*>(&r1.x), p0);
    p1 = __hfma2(h1, *reinterpret_cast<const __half2*>(&r1.y), p1);
    p2 = __hfma2(h1, *reinterpret_cast<const __half2*>(&r1.z), p2);
    p3 = __hfma2(h1, *reinterpret_cast<const __half2*>(&r1.w), p3);
    p0 = __hfma2(h2, *reinterpret_cast<const __half2*>(&r2.x), p0);
    p1 = __hfma2(h2, *reinterpret_cast<const __half2*>(&r2.y), p1);
    p2 = __hfma2(h2, *reinterpret_cast<const __half2*>(&r2.z), p2);
    p3 = __hfma2(h2, *reinterpret_cast<const __half2*>(&r2.w), p3);
    p0 = __hfma2(h3, *reinterpret_cast<const __half2*>(&r3.x), p0);
    p1 = __hfma2(h3, *reinterpret_cast<const __half2*>(&r3.y), p1);
    p2 = __hfma2(h3, *reinterpret_cast<const __half2*>(&r3.z), p2);
    p3 = __hfma2(h3, *reinterpret_cast<const __half2*>(&r3.w), p3);
    float2 f;
    f = __half22float2(p0);  aA.x += f.x;  aA.y += f.y;
    f = __half22float2(p1);  aA.z += f.x;  aA.w += f.y;
    f = __half22float2(p2);  aB.x += f.x;  aB.y += f.y;
    f = __half22float2(p3);  aB.z += f.x;  aB.w += f.y;
}

// SpMM: one quarter-warp (8 lanes) per output row, fp16 table.
// Main loop: 8 edges — ALL 8 LDG.128 gathers issued before any consume
// (MLP=8 per quarter; launch_bounds(256,4) allows ~64 regs so ptxas keeps
// them in flight). Two depth-4 half2 chains + drains: numerics identical
// to the 4-edge champion. Odd-peel only (int2/float2 are 8B-aligned).
// Tail: one 4-edge group + <=3 fp32 edges.
__global__ void __launch_bounds__(256, 4) spmm_qwarp_per_row(
    const int*   __restrict__ cols,
    const float* __restrict__ vals,
    float*       __restrict__ out)
{
    int row   = (blockIdx.x * blockDim.x + threadIdx.x) >> 3;
    int lane8 = threadIdx.x & 7;
    if (row >= N_NODES) return;

    int e  = g_row_ptr[row];
    int hi = g_row_ptr[row + 1];

    const uint4* __restrict__ emb = reinterpret_cast<const uint4*>(g_emb_h);

    float4 aA = make_float4(0.f, 0.f, 0.f, 0.f);
    float4 aB = make_float4(0.f, 0.f, 0.f, 0.f);

    // peel one edge if start is odd (enables 8B-aligned packed loads)
    if ((e & 1) && e < hi) {
        edge_f32(emb, cols, vals, e, lane8, aA, aB);
        ++e;
    }

    // main loop: 8 edges, 8 gathers in flight
    for (; e + 7 < hi; e += 8) {
        int2   c01 = *reinterpret_cast<const int2*>(cols + e);
        int2   c23 = *reinterpret_cast<const int2*>(cols + e + 2);
        int2   c45 = *reinterpret_cast<const int2*>(cols + e + 4);
        int2   c67 = *reinterpret_cast<const int2*>(cols + e + 6);
        float2 v01 = *reinterpret_cast<const float2*>(vals + e);
        float2 v23 = *reinterpret_cast<const float2*>(vals + e + 2);
        float2 v45 = *reinterpret_cast<const float2*>(vals + e + 4);
        float2 v67 = *reinterpret_cast<const float2*>(vals + e + 6);

        uint4 r0 = emb[(size_t)c01.x * 8 + lane8];
        uint4 r1 = emb[(size_t)c01.y * 8 + lane8];
        uint4 r2 = emb[(size_t)c23.x * 8 + lane8];
        uint4 r3 = emb[(size_t)c23.y * 8 + lane8];
        uint4 r4 = emb[(size_t)c45.x * 8 + lane8];
        uint4 r5 = emb[(size_t)c45.y * 8 + lane8];
        uint4 r6 = emb[(size_t)c67.x * 8 + lane8];
        uint4 r7 = emb[(size_t)c67.y * 8 + lane8];

        chain4_drain(r0, r1, r2, r3,
                     __float2half2_rn(v01.x), __float2half2_rn(v01.y),
                     __float2half2_rn(v23.x), __float2half2_rn(v23.y),
                     aA, aB);
        chain4_drain(r4, r5, r6, r7,
                     __float2half2_rn(v45.x), __float2half2_rn(v45.y),
                     __float2half2_rn(v67.x), __float2half2_rn(v67.y),
                     aA, aB);
    }

    // tail: one 4-edge group
    if (e + 3 < hi) {
        int2   c01 = *reinterpret_cast<const int2*>(cols + e);
        int2   c23 = *reinterpret_cast<const int2*>(cols + e + 2);
        float2 v01 = *reinterpret_cast<const float2*>(vals + e);
        float2 v23 = *reinterpret_cast<const float2*>(vals + e + 2);
        uint4 r0 = emb[(size_t)c01.x * 8 + lane8];
        uint4 r1 = emb[(size_t)c01.y * 8 + lane8];
        uint4 r2 = emb[(size_t)c23.x * 8 + lane8];
        uint4 r3 = emb[(size_t)c23.y * 8 + lane8];
        chain4_drain(r0, r1, r2, r3,
                     __float2half2_rn(v01.x), __float2half2_rn(v01.y),
                     __float2half2_rn(v23.x), __float2half2_rn(v23.y),
                     aA, aB);
        e += 4;
    }
    // tail (<=3 edges): exact fp32 path
    for (; e < hi; ++e) {
        edge_f32(emb, cols, vals, e, lane8, aA, aB);
    }

    // 8 lanes x 32B = 256B coalesced output row
    float4* o = reinterpret_cast<float4*>(out) + (size_t)row * 16 + lane8 * 2;
    o[0] = aA;
    o[1] = aB;
}

extern "C" void kernel_launch(void* const* d_in, const int* in_sizes, int n_in,
                              void* d_out, int out_size) {
    const int*   rows   = (const int*)d_in[0];
    const int*   cols   = (const int*)d_in[1];
    const float* vals   = (const float*)d_in[2];
    const float* embeds = (const float*)d_in[3];
    float*       out    = (float*)d_out;

    int n_edges = in_sizes[0];

    {
        int total = n_edges;  // covers both tasks (convert needs 400k)
        int threads = 256;
        prep_kernel<<<(total + threads - 1) / threads, threads>>>(embeds, rows, n_edges);
    }
    {
        int threads = 256;
        int blocks = (N_NODES * 8 + threads - 1) / threads;
        spmm_qwarp_per_row<<<blocks, threads>>>(cols, vals, out);
    }
}

// round 15
// speedup vs baseline: 1.1115x; 1.1115x over previous
#include <cuda_runtime.h>
#include <cuda_fp16.h>
#include <stdint.h>

#define N_NODES 100000
#define N_EDGES 1600000
#define D_FEAT  64

// Scratch (device globals — no allocs allowed):
__device__ int    g_row_ptr[N_NODES + 1];
__device__ __half g_emb_h[N_NODES * D_FEAT];   // 12.8 MB fp16 shadow (128B per row)

// Merged prep, 400k threads total:
//  Task 1: fp32->fp16 convert, 16 floats/thread (4 independent float4 loads).
//  Task 2: CSR boundary fill, 4 edges/thread (one int4 + one scalar load).
__global__ void __launch_bounds__(256) prep_kernel(
    const float* __restrict__ embeds,
    const int*   __restrict__ rows,
    int n_edges) {
    int i = blockIdx.x * blockDim.x + threadIdx.x;

    // Task 1: convert 16 floats -> 16 halfs
    if (i < N_NODES * D_FEAT / 16) {
        const float4* src = reinterpret_cast<const float4*>(embeds) + (size_t)i * 4;
        float4 f0 = src[0];
        float4 f1 = src[1];
        float4 f2 = src[2];
        float4 f3 = src[3];
        union { __half2 h[4]; uint4 u; } a, b;
        a.h[0] = __floats2half2_rn(f0.x, f0.y);
        a.h[1] = __floats2half2_rn(f0.z, f0.w);
        a.h[2] = __floats2half2_rn(f1.x, f1.y);
        a.h[3] = __floats2half2_rn(f1.z, f1.w);
        b.h[0] = __floats2half2_rn(f2.x, f2.y);
        b.h[1] = __floats2half2_rn(f2.z, f2.w);
        b.h[2] = __floats2half2_rn(f3.x, f3.y);
        b.h[3] = __floats2half2_rn(f3.z, f3.w);
        reinterpret_cast<uint4*>(g_emb_h)[i * 2]     = a.u;
        reinterpret_cast<uint4*>(g_emb_h)[i * 2 + 1] = b.u;
    }

    // Task 2: boundary fill for edges [4i, 4i+4)  (rows sorted, n_edges % 4 == 0)
    int e0 = i * 4;
    if (e0 < n_edges) {
        int4 r4 = *reinterpret_cast<const int4*>(rows + e0);
        int prev = (e0 == 0) ? -1 : rows[e0 - 1];

        int rr;
        for (rr = prev + 1;  rr <= r4.x; ++rr) g_row_ptr[rr] = e0;
        for (rr = r4.x + 1;  rr <= r4.y; ++rr) g_row_ptr[rr] = e0 + 1;
        for (rr = r4.y + 1;  rr <= r4.z; ++rr) g_row_ptr[rr] = e0 + 2;
        for (rr = r4.z + 1;  rr <= r4.w; ++rr) g_row_ptr[rr] = e0 + 3;

        if (e0 + 4 >= n_edges) {
            for (rr = r4.w + 1; rr <= N_NODES; ++rr) g_row_ptr[rr] = n_edges;
        }
    }
}

// fp32-exact single-edge accumulate (peel/tail path).
__device__ __forceinline__ void edge_f32(const uint4* __restrict__ emb,
                                         const int* __restrict__ cols,
                                         const float* __restrict__ vals,
                                         int e, int lane8,
                                         float4& aA, float4& aB) {
    int   c = cols[e];
    float v = vals[e];
    uint4 r = emb[(size_t)c * 8 + lane8];
    float2 f0 = __half22float2(*reinterpret_cast<__half2*>(&r.x));
    float2 f1 = __half22float2(*reinterpret_cast<__half2*>(&r.y));
    float2 f2 = __half22float2(*reinterpret_cast<__half2*>(&r.z));
    float2 f3 = __half22float2(*reinterpret_cast<__half2*>(&r.w));
    aA.x += v * f0.x;  aA.y += v * f0.y;
    aA.z += v * f1.x;  aA.w += v * f1.y;
    aB.x += v * f2.x;  aB.y += v * f2.y;
    aB.z += v * f3.x;  aB.w += v * f3.y;
}

// SpMM: one quarter-warp (8 lanes) per output row, fp16 table.
// EXACT champion structure (R7): 4-edge groups, depth-4 half2 accumulation,
// fp32 drain per group, odd-peel for 8B-aligned packed index loads.
__global__ void __launch_bounds__(256) spmm_qwarp_per_row(
    const int*   __restrict__ cols,
    const float* __restrict__ vals,
    float*       __restrict__ out)
{
    int row   = (blockIdx.x * blockDim.x + threadIdx.x) >> 3;
    int lane8 = threadIdx.x & 7;
    if (row >= N_NODES) return;

    int e  = g_row_ptr[row];
    int hi = g_row_ptr[row + 1];

    const uint4* __restrict__ emb = reinterpret_cast<const uint4*>(g_emb_h);

    float4 aA = make_float4(0.f, 0.f, 0.f, 0.f);
    float4 aB = make_float4(0.f, 0.f, 0.f, 0.f);

    // peel one edge if start is odd (enables int2/float2 packed loads)
    if ((e & 1) && e < hi) {
        edge_f32(emb, cols, vals, e, lane8, aA, aB);
        ++e;
    }

    // main loop: 4 edges per group, half2 accumulation, drain each group
    for (; e + 3 < hi; e += 4) {
        int2   c01 = *reinterpret_cast<const int2*>(cols + e);
        int2   c23 = *reinterpret_cast<const int2*>(cols + e + 2);
        float2 v01 = *reinterpret_cast<const float2*>(vals + e);
        float2 v23 = *reinterpret_cast<const float2*>(vals + e + 2);

        uint4 r0 = emb[(size_t)c01.x * 8 + lane8];
        uint4 r1 = emb[(size_t)c01.y * 8 + lane8];
        uint4 r2 = emb[(size_t)c23.x * 8 + lane8];
        uint4 r3 = emb[(size_t)c23.y * 8 + lane8];

        __half2 h0 = __float2half2_rn(v01.x);
        __half2 h1 = __float2half2_rn(v01.y);
        __half2 h2 = __float2half2_rn(v23.x);
        __half2 h3 = __float2half2_rn(v23.y);

        __half2 p0 = __hmul2(h0, *reinterpret_cast<__half2*>(&r0.x));
        __half2 p1 = __hmul2(h0, *reinterpret_cast<__half2*>(&r0.y));
        __half2 p2 = __hmul2(h0, *reinterpret_cast<__half2*>(&r0.z));
        __half2 p3 = __hmul2(h0, *reinterpret_cast<__half2*>(&r0.w));

        p0 = __hfma2(h1, *reinterpret_cast<__half2*>(&r1.x), p0);
        p1 = __hfma2(h1, *reinterpret_cast<__half2*>(&r1.y), p1);
        p2 = __hfma2(h1, *reinterpret_cast<__half2*>(&r1.z), p2);
        p3 = __hfma2(h1, *reinterpret_cast<__half2*>(&r1.w), p3);

        p0 = __hfma2(h2, *reinterpret_cast<__half2*>(&r2.x), p0);
        p1 = __hfma2(h2, *reinterpret_cast<__half2*>(&r2.y), p1);
        p2 = __hfma2(h2, *reinterpret_cast<__half2*>(&r2.z), p2);
        p3 = __hfma2(h2, *reinterpret_cast<__half2*>(&r2.w), p3);

        p0 = __hfma2(h3, *reinterpret_cast<__half2*>(&r3.x), p0);
        p1 = __hfma2(h3, *reinterpret_cast<__half2*>(&r3.y), p1);
        p2 = __hfma2(h3, *reinterpret_cast<__half2*>(&r3.z), p2);
        p3 = __hfma2(h3, *reinterpret_cast<__half2*>(&r3.w), p3);

        // drain group to fp32
        float2 f;
        f = __half22float2(p0);  aA.x += f.x;  aA.y += f.y;
        f = __half22float2(p1);  aA.z += f.x;  aA.w += f.y;
        f = __half22float2(p2);  aB.x += f.x;  aB.y += f.y;
        f = __half22float2(p3);  aB.z += f.x;  aB.w += f.y;
    }

    // tail (<=3 edges): exact fp32 path
    for (; e < hi; ++e) {
        edge_f32(emb, cols, vals, e, lane8, aA, aB);
    }

    // 8 lanes x 32B = 256B coalesced output row
    float4* o = reinterpret_cast<float4*>(out) + (size_t)row * 16 + lane8 * 2;
    o[0] = aA;
    o[1] = aB;
}

extern "C" void kernel_launch(void* const* d_in, const int* in_sizes, int n_in,
                              void* d_out, int out_size) {
    const int*   rows   = (const int*)d_in[0];
    const int*   cols   = (const int*)d_in[1];
    const float* vals   = (const float*)d_in[2];
    const float* embeds = (const float*)d_in[3];
    float*       out    = (float*)d_out;

    int n_edges = in_sizes[0];

    {
        int conv_threads = N_NODES * D_FEAT / 16;          // 400000
        int fill_threads = (n_edges + 3) / 4;              // 400000
        int total = conv_threads > fill_threads ? conv_threads : fill_threads;
        int threads = 256;
        prep_kernel<<<(total + threads - 1) / threads, threads>>>(embeds, rows, n_edges);
    }
    {
        int threads = 256;
        int blocks = (N_NODES * 8 + threads - 1) / threads;
        spmm_qwarp_per_row<<<blocks, threads>>>(cols, vals, out);
    }
}